// round 5
// baseline (speedup 1.0000x reference)
#include <cuda_runtime.h>
#include <math_constants.h>
#include <stdint.h>

#define B  32
#define N  8192
#define K  128
#define PS 32

#define BINS  512        // key >> 23 (exponent + 1 mantissa bit)
#define CAPK  384
#define RPC   2
#define SRANK 5          // sample rank -> ~population rank 160

typedef unsigned long long u64;

// Scratch (allocation-free rule: __device__ globals)
__device__ int   g_fps_idx[B * K];
__device__ float g_centers[B * K * 3];
__device__ int   g_knn[B * K * PS];

// ---------------------------------------------------------------------------
// f32x2 packed helpers (one fma-pipe instr = 2 IEEE .rn ops, bit-identical)
// ---------------------------------------------------------------------------
__device__ __forceinline__ u64 pack2(float lo, float hi) {
    u64 r; asm("mov.b64 %0, {%1, %2};" : "=l"(r) : "f"(lo), "f"(hi)); return r;
}
__device__ __forceinline__ float2 unpack2(u64 v) {
    float2 f; asm("mov.b64 {%0, %1}, %2;" : "=f"(f.x), "=f"(f.y) : "l"(v)); return f;
}
__device__ __forceinline__ u64 add2(u64 a, u64 b) {
    u64 d; asm("add.rn.f32x2 %0, %1, %2;" : "=l"(d) : "l"(a), "l"(b)); return d;
}
__device__ __forceinline__ u64 mul2(u64 a, u64 b) {
    u64 d; asm("mul.rn.f32x2 %0, %1, %2;" : "=l"(d) : "l"(a), "l"(b)); return d;
}
__device__ __forceinline__ u64 fma2(u64 a, u64 b, u64 c) {
    u64 d; asm("fma.rn.f32x2 %0, %1, %2, %3;" : "=l"(d) : "l"(a), "l"(b), "l"(c)); return d;
}

// ---------------------------------------------------------------------------
// FPS: one block/batch, 1024 threads, 8 pts/thread, f32x2 math.
// argmax: value REDUX + smem atomicMax; equality scan GUARDED to warps that
// hold the max (warp-uniform), then atomicMin on index (lowest-index ties).
// ---------------------------------------------------------------------------
extern "C" __global__ void __launch_bounds__(1024, 1)
fps_kernel(const float* __restrict__ points) {
    extern __shared__ float pts[];      // [N*3] = 96KB
    __shared__ unsigned s_maxb[K];
    __shared__ int      s_idx[K];

    const int b = blockIdx.x;
    const int t = threadIdx.x;
    const float* gp = points + (size_t)b * N * 3;

    for (int i = t; i < N * 3; i += 1024) pts[i] = gp[i];
    if (t < K) { s_maxb[t] = 0u; s_idx[t] = 0x7fffffff; }
    __syncthreads();

    u64 px2[4], py2[4], pz2[4];
    float md[8];
#pragma unroll
    for (int j = 0; j < 4; j++) {
        int nlo = t + (2 * j) * 1024;
        int nhi = t + (2 * j + 1) * 1024;
        px2[j] = pack2(pts[3 * nlo + 0], pts[3 * nhi + 0]);
        py2[j] = pack2(pts[3 * nlo + 1], pts[3 * nhi + 1]);
        pz2[j] = pack2(pts[3 * nlo + 2], pts[3 * nhi + 2]);
        md[2 * j] = CUDART_INF_F; md[2 * j + 1] = CUDART_INF_F;
    }

    int cur = 0;
    const int lane = t & 31;
    for (int k = 0; k < K; k++) {
        float cx = pts[3 * cur + 0];
        float cy = pts[3 * cur + 1];
        float cz = pts[3 * cur + 2];
        if (t == 0) {
            g_fps_idx[b * K + k] = cur;
            g_centers[(b * K + k) * 3 + 0] = cx;
            g_centers[(b * K + k) * 3 + 1] = cy;
            g_centers[(b * K + k) * 3 + 2] = cz;
        }
        u64 nc2x = pack2(-cx, -cx);
        u64 nc2y = pack2(-cy, -cy);
        u64 nc2z = pack2(-cz, -cz);
#pragma unroll
        for (int j = 0; j < 4; j++) {
            u64 dx = add2(px2[j], nc2x);
            u64 dy = add2(py2[j], nc2y);
            u64 dz = add2(pz2[j], nc2z);
            u64 d  = mul2(dx, dx);
            d = fma2(dy, dy, d);
            d = fma2(dz, dz, d);
            float2 f = unpack2(d);
            md[2 * j]     = fminf(md[2 * j],     f.x);
            md[2 * j + 1] = fminf(md[2 * j + 1], f.y);
        }
        float tv = fmaxf(fmaxf(fmaxf(md[0], md[1]), fmaxf(md[2], md[3])),
                         fmaxf(fmaxf(md[4], md[5]), fmaxf(md[6], md[7])));
        unsigned wv = __reduce_max_sync(0xffffffffu, __float_as_uint(tv));
        if (lane == 0) atomicMax(&s_maxb[k], wv);
        __syncthreads();
        const unsigned mb = s_maxb[k];
        if (wv == mb) {           // warp-uniform: only max-holding warps scan
            int li = 0x7fffffff;
#pragma unroll
            for (int s = 0; s < 8; s++) {
                if (__float_as_uint(md[s]) == mb) li = min(li, t + s * 1024);
            }
            if (li != 0x7fffffff) atomicMin(&s_idx[k], li);
        }
        __syncthreads();
        cur = s_idx[k];
    }
}

// ---------------------------------------------------------------------------
// KNN: 2 rows per CTA (grid 2048, 256 threads). Keys stored to SMEM (no
// per-point atomics). Sample-histogram threshold, grow/shrink verify, warp-
// aggregated collect, exact stable rank sort. Exact fallback for tie storms.
// ---------------------------------------------------------------------------
__device__ __forceinline__ unsigned f2key(float f) {
    unsigned bits = __float_as_uint(f);
    return (bits & 0x80000000u) ? ~bits : (bits | 0x80000000u);
}

extern "C" __global__ void __launch_bounds__(256)
knn_kernel(const float* __restrict__ points) {
    extern __shared__ char sm[];
    unsigned* s_key  = (unsigned*)sm;                                  // RPC*N (64KB)
    unsigned* s_hist = (unsigned*)(sm + RPC * N * 4);                  // RPC*BINS (4KB)
    int*      s_cidx = (int*)(sm + RPC * N * 4 + RPC * BINS * 4);      // CAPK
    unsigned* s_ckey = (unsigned*)(sm + RPC * N * 4 + RPC * BINS * 4 + CAPK * 4);

    __shared__ unsigned s_wsum[8];
    __shared__ int      s_T;
    __shared__ int      s_cnt;
    __shared__ u64      s_min8[8];
    __shared__ u64      s_last;

    const int row0 = blockIdx.x * RPC;
    const int b    = row0 >> 7;
    const int t    = threadIdx.x;
    const int lane = t & 31, w = t >> 5;
    const unsigned lmask_lt = (1u << lane) - 1u;
    const float* gp = points + (size_t)b * N * 3;

    float cx[RPC], cy[RPC], cz[RPC], cc[RPC];
#pragma unroll
    for (int r = 0; r < RPC; r++) {
        const float* c = &g_centers[(row0 + r) * 3];
        cx[r] = c[0]; cy[r] = c[1]; cz[r] = c[2];
        cc[r] = cx[r] * cx[r] + cy[r] * cy[r] + cz[r] * cz[r];
    }

    for (int i = t; i < RPC * BINS; i += 256) s_hist[i] = 0u;
    __syncthreads();

    // Pass 1: keys -> smem; sample histogram only for n = t (j==0)
#pragma unroll
    for (int j = 0; j < N / 256; j++) {
        int n = t + j * 256;
        float px = gp[3 * n + 0], py = gp[3 * n + 1], pz = gp[3 * n + 2];
        float pp = px * px + py * py + pz * pz;
#pragma unroll
        for (int r = 0; r < RPC; r++) {
            float dot = cx[r] * px + cy[r] * py + cz[r] * pz;
            float d2  = (cc[r] + pp) - 2.0f * dot;
            unsigned key = f2key(d2);
            s_key[r * N + n] = key;
            if (j == 0) atomicAdd(&s_hist[r * BINS + (key >> 23)], 1u);
        }
    }
    __syncthreads();

    for (int r = 0; r < RPC; r++) {
        const unsigned* keyrow = &s_key[r * N];
        int* out = &g_knn[(row0 + r) * PS];

        // --- threshold bin from sample (first bin with cum >= SRANK) ---
        {
            unsigned c0 = s_hist[r * BINS + 2 * t];
            unsigned c1 = s_hist[r * BINS + 2 * t + 1];
            unsigned seg = c0 + c1, pre = seg;
#pragma unroll
            for (int off = 1; off < 32; off <<= 1) {
                unsigned v = __shfl_up_sync(0xffffffffu, pre, off);
                if (lane >= off) pre += v;
            }
            if (lane == 31) s_wsum[w] = pre;
            __syncthreads();
            unsigned wbase = 0;
            for (int i = 0; i < w; i++) wbase += s_wsum[i];
            unsigned excl = wbase + pre - seg;
            if (excl < SRANK && excl + seg >= SRANK)
                s_T = (excl + c0 >= SRANK) ? 2 * t : 2 * t + 1;
            __syncthreads();
        }
        int T = s_T;

        // --- verify/adjust: grow while cnt<PS, shrink while cnt>CAPK ---
        int cnt;
        bool giant_tie = false;
        while (true) {
            if (t == 0) s_cnt = 0;
            __syncthreads();
            unsigned Tmax = ((unsigned)(T + 1) << 23) - 1u;
            int c = 0;
#pragma unroll
            for (int j = 0; j < N / 256; j++)
                c += (keyrow[t + j * 256] <= Tmax);
            c = __reduce_add_sync(0xffffffffu, c);
            if (lane == 0) atomicAdd(&s_cnt, c);
            __syncthreads();
            cnt = s_cnt;
            if (cnt >= PS && cnt <= CAPK) break;
            if (cnt < PS) {
                if (T >= BINS - 1) { giant_tie = true; break; }  // after a shrink
                T = min(BINS - 1, T + 2);
            } else {
                if (T == 0) { giant_tie = true; break; }
                T -= 1;
            }
            __syncthreads();
        }
        __syncthreads();

        if (!giant_tie) {
            // --- collect survivors (warp-aggregated atomics) ---
            if (t == 0) s_cnt = 0;
            __syncthreads();
            unsigned Tmax = ((unsigned)(T + 1) << 23) - 1u;
#pragma unroll
            for (int j = 0; j < N / 256; j++) {
                int n = t + j * 256;
                unsigned key = keyrow[n];
                bool p = (key <= Tmax);
                unsigned m = __ballot_sync(0xffffffffu, p);
                if (m) {
                    int leader = __ffs(m) - 1;
                    int base = 0;
                    if (lane == leader) base = atomicAdd(&s_cnt, __popc(m));
                    base = __shfl_sync(0xffffffffu, base, leader);
                    if (p) {
                        int pos = base + __popc(m & lmask_lt);
                        s_cidx[pos] = n;
                        s_ckey[pos] = key;
                    }
                }
            }
            __syncthreads();
            const int C = s_cnt;
            // --- exact stable rank sort over C candidates ---
            for (int jj = t; jj < C; jj += 256) {
                unsigned kj = s_ckey[jj];
                int      nj = s_cidx[jj];
                int rk = 0;
                for (int m = 0; m < C; m++) {
                    unsigned km = s_ckey[m];
                    rk += (km < kj) || (km == kj && s_cidx[m] < nj);
                }
                if (rk < PS) out[rk] = nj;
            }
        } else {
            // --- exact fallback: 32 sequential lexicographic mins ---
            if (t == 0) s_last = 0ull;
            __syncthreads();
            for (int sel = 0; sel < PS; sel++) {
                u64 last = s_last;
                u64 best = 0xffffffffffffffffull;
#pragma unroll
                for (int j = 0; j < N / 256; j++) {
                    int n = t + j * 256;
                    u64 v = ((u64)keyrow[n] << 32) | (unsigned)n;
                    if (v > last && v < best) best = v;
                }
#pragma unroll
                for (int off = 16; off; off >>= 1) {
                    u64 o = __shfl_down_sync(0xffffffffu, best, off);
                    best = o < best ? o : best;
                }
                if (lane == 0) s_min8[w] = best;
                __syncthreads();
                if (t == 0) {
                    u64 m = s_min8[0];
                    for (int i = 1; i < 8; i++) m = s_min8[i] < m ? s_min8[i] : m;
                    out[sel] = (int)(unsigned)(m & 0xffffffffu);
                    s_last = m;
                }
                __syncthreads();
            }
        }
        __syncthreads();
    }
}

// ---------------------------------------------------------------------------
// Epilogues
// ---------------------------------------------------------------------------
extern "C" __global__ void epilogue_i32(int* __restrict__ out, int out_size) {
    int i = blockIdx.x * 256 + threadIdx.x;
    if (i < out_size && i < B * K * PS) out[i] = g_knn[i];
}

extern "C" __global__ void epilogue_f32(float* __restrict__ out, int out_size) {
    int i = blockIdx.x * 256 + threadIdx.x;
    if (i >= out_size) return;
    if (i < B * K * PS) {
        out[i] = (float)g_knn[i];
    } else if (i < B * K * PS + B * K * 3) {
        out[i] = g_centers[i - B * K * PS];
    }
}

// ---------------------------------------------------------------------------
extern "C" void kernel_launch(void* const* d_in, const int* in_sizes, int n_in,
                              void* d_out, int out_size) {
    (void)in_sizes; (void)n_in;
    const float* points = (const float*)d_in[0];

    const int fps_smem = N * 3 * (int)sizeof(float);
    const int knn_smem = RPC * N * 4 + RPC * BINS * 4 + CAPK * 4 * 2;

    cudaFuncSetAttribute(fps_kernel,
                         cudaFuncAttributeMaxDynamicSharedMemorySize, fps_smem);
    cudaFuncSetAttribute(knn_kernel,
                         cudaFuncAttributeMaxDynamicSharedMemorySize, knn_smem);

    fps_kernel<<<B, 1024, fps_smem>>>(points);
    knn_kernel<<<B * K / RPC, 256, knn_smem>>>(points);

    if (out_size == B * K * PS) {
        int total = B * K * PS;
        epilogue_i32<<<(total + 255) / 256, 256>>>((int*)d_out, out_size);
    } else {
        int total = B * K * PS + B * K * 3;
        int n = total < out_size ? out_size : total;
        epilogue_f32<<<(n + 255) / 256, 256>>>((float*)d_out, out_size);
    }
}